// round 6
// baseline (speedup 1.0000x reference)
#include <cuda_runtime.h>

// ---------------- problem constants ----------------
#define NXg 256
#define NYg 256
#define NG  (NXg*NYg)

// tile: interior 16(x) x 32(y), halo 4 -> ext 24x40; strips of 2 in y
#define IXt 16
#define IYt 32
#define Hh  4
#define EXt 24
#define EYt 40
#define EXT (EXt*EYt)      // 960
#define SW   2
#define NSTR (EYt/SW)      // 20
#define ACT  (EXt*NSTR)    // 480 active threads
#define NT   512
#define NBX (NYg/IYt)      // 8
#define NBY (NXg/IXt)      // 16
#define NCTA (NBX*NBY)     // 128 CTAs <= 148 SMs -> co-resident
#define RELAX  100
#define TSTEPS 1024

typedef unsigned long long u64;

// ---------------- packed f32x2 helpers ----------------
__device__ __forceinline__ u64 f2pk(float lo, float hi){
    u64 r; unsigned a = __float_as_uint(lo), b = __float_as_uint(hi);
    asm("mov.b64 %0,{%1,%2};" : "=l"(r) : "r"(a), "r"(b)); return r;
}
__device__ __forceinline__ void f2up(u64 v, float& lo, float& hi){
    unsigned a, b; asm("mov.b64 {%0,%1},%2;" : "=r"(a), "=r"(b) : "l"(v));
    lo = __uint_as_float(a); hi = __uint_as_float(b);
}
__device__ __forceinline__ u64 f2add(u64 a, u64 b){
    u64 d; asm("add.rn.f32x2 %0,%1,%2;" : "=l"(d) : "l"(a), "l"(b)); return d;
}
__device__ __forceinline__ u64 f2mul(u64 a, u64 b){
    u64 d; asm("mul.rn.f32x2 %0,%1,%2;" : "=l"(d) : "l"(a), "l"(b)); return d;
}
__device__ __forceinline__ u64 f2fma(u64 a, u64 b, u64 c){
    u64 d; asm("fma.rn.f32x2 %0,%1,%2,%3;" : "=l"(d) : "l"(a), "l"(b), "l"(c)); return d;
}
__device__ __forceinline__ u64 f2neg(u64 a){ return a ^ 0x8000000080000000ULL; }

// ---------------- device state ----------------
__device__ __align__(16) float g_m[2][3*NG];
__device__ unsigned g_count;
__device__ unsigned g_sense;     // even flips per run -> replay-safe

__device__ __forceinline__ void gridbar(unsigned& lsense)
{
    __syncthreads();
    if (threadIdx.x == 0) {
        unsigned s = lsense ^ 1u;
        lsense = s;
        unsigned old;
        asm volatile("atom.add.acq_rel.gpu.u32 %0, [%1], 1;"
                     : "=r"(old) : "l"(&g_count) : "memory");
        if (old == NCTA - 1u) {
            asm volatile("st.relaxed.gpu.u32 [%0], %1;" :: "l"(&g_count), "r"(0u) : "memory");
            asm volatile("st.release.gpu.u32 [%0], %1;" :: "l"(&g_sense), "r"(s) : "memory");
        } else {
            unsigned v;
            do {
                asm volatile("ld.acquire.gpu.u32 %0, [%1];" : "=r"(v) : "l"(&g_sense) : "memory");
            } while (v != s);
        }
    }
    __syncthreads();
}

__global__ void __launch_bounds__(NT, 1)
k_sim(const float* __restrict__ sig,  const float* __restrict__ Bext,
      const float* __restrict__ Msat, const float* __restrict__ src,
      const float* __restrict__ pmask, float* __restrict__ out)
{
    __shared__ __align__(16) float SA[3][EXT];
    __shared__ __align__(16) float SB[3][EXT];
    __shared__ float red[NT/32];
    __shared__ float s_pminv;
    __shared__ float s_sig[TSTEPS];

    const int tid = threadIdx.x;
    const bool live = (tid < ACT);
    const int ex  = live ? tid / NSTR : 0;
    const int sy  = live ? tid % NSTR : 0;
    const int gx0 = (int)blockIdx.y * IXt - Hh;
    const int gy0 = (int)blockIdx.x * IYt - Hh;
    const int gx  = gx0 + ex;
    const int gyb = gy0 + SW*sy;
    const int e   = ex*EYt + SW*sy;

    const int gxc = min(max(gx, 0), NXg - 1);
    const int gyc = min(max(gyb, 0), NYg - SW);
    const int g   = gxc*NYg + gyc;

    const int exm = (ex == 0       || gx <= 0)       ? ex : ex - 1;
    const int exq = (ex == EXt - 1 || gx >= NXg - 1) ? ex : ex + 1;
    const int emb = exm*EYt + SW*sy;
    const int epb = exq*EYt + SW*sy;
    const int yL = (sy == 0        || gyb <= 0)                ? e          : e - 1;
    const int yR = (sy == NSTR - 1 || gyb + SW - 1 >= NYg - 1) ? e + SW - 1 : e + SW;

    const bool sint = live && ex >= Hh && ex < Hh + IXt && sy >= Hh/SW && sy < (Hh + IYt)/SW;
    const bool ring = sint && (ex < Hh + 4 || ex >= Hh + IXt - 4 ||
                               sy < Hh/SW + 2 || sy >= (Hh + IYt)/SW - 2);

    const float MU0f    = (float)(4e-7 * 3.14159265358979323846);
    const float TWO_A   = (float)(2.0 * 3.65e-12);
    const float INV_DX2 = (float)(1.0 / (50e-9 * 50e-9));
    const double hd  = 1.7595e11 * 5e-12;
    const float c05f = (float)(0.5 * hd);
    const float cflf = (float)hd;
    const float h6f  = (float)(hd / 6.0);
    const float a_rx = 0.5f,  i_rx = (float)(1.0 / (1.0 + 0.5 * 0.5));
    const float a_rn = 0.01f, i_rn = (float)(1.0 / (1.0 + 0.01 * 0.01));

    // -------- static per-cell constants, packed (registers, whole run) --------
    float pmw[SW], m0x[SW];
    float cB[3][SW], cS[3][SW], cCL[SW], cDg[SW];
    int anyp = 0;
    #pragma unroll
    for (int j = 0; j < SW; j++) {
        int gyj = gyb + j;
        bool ok = live && gx >= 0 && gx < NXg && gyj >= 0 && gyj < NYg;
        int gj = ok ? gx*NYg + gyj : g;
        float ms = Msat[gj];
        cCL[j] = (TWO_A / ms) * INV_DX2;
        cDg[j] = MU0f * ms;
        cB[0][j] = Bext[0*NG + gj]; cB[1][j] = Bext[1*NG + gj]; cB[2][j] = Bext[2*NG + gj];
        cS[0][j] = src [0*NG + gj]; cS[1][j] = src [1*NG + gj]; cS[2][j] = src [2*NG + gj];
        float pv = (sint && ok) ? pmask[gj] : 0.f;
        pmw[j] = pv * ms;
        m0x[j] = 0.f;
        if (pv != 0.f) anyp = 1;
    }
    const u64 rB0 = f2pk(cB[0][0], cB[0][1]), rB1 = f2pk(cB[1][0], cB[1][1]), rB2 = f2pk(cB[2][0], cB[2][1]);
    const u64 rS0 = f2pk(cS[0][0], cS[0][1]), rS1 = f2pk(cS[1][0], cS[1][1]), rS2 = f2pk(cS[2][0], cS[2][1]);
    const u64 rCL2 = f2pk(cCL[0], cCL[1]);
    const u64 nDg2 = f2pk(-cDg[0], -cDg[1]);
    const u64 neg4 = f2pk(-4.f, -4.f);
    const u64 h62  = f2pk(h6f, h6f);
    const u64 c052 = f2pk(c05f, c05f);
    const u64 cfl2 = f2pk(cflf, cflf);
    const u64 one2 = f2pk(1.f, 1.f);
    const u64 two2 = f2pk(2.f, 2.f);

    for (int i = tid; i < TSTEPS; i += NT) s_sig[i] = sig[i];
    if (blockIdx.x == 0 && blockIdx.y == 0)
        for (int i = tid; i < TSTEPS; i += NT) out[i] = 0.f;

    const int hasp = __syncthreads_or(anyp);
    if (hasp) {
        float s = 0.f;
        for (int i = tid; i < NG; i += NT) s += pmask[i];
        #pragma unroll
        for (int o = 16; o; o >>= 1) s += __shfl_down_sync(0xffffffffu, s, o);
        if ((tid & 31) == 0) red[tid >> 5] = s;
        __syncthreads();
        if (tid < 32) {
            float v = (tid < NT/32) ? red[tid] : 0.f;
            #pragma unroll
            for (int o = 8; o; o >>= 1) v += __shfl_down_sync(0xffffffffu, v, o);
            if (tid == 0) s_pminv = 1.f / v;
        }
    }
    __syncthreads();

    // m carried packed in registers between steps
    u64 mb0 = f2pk(0.f, 0.f), mb1 = f2pk(0.f, 0.f), mb2 = f2pk(1.f, 1.f);
    if (live) {
        *(u64*)&SA[0][e] = mb0; *(u64*)&SA[1][e] = mb1; *(u64*)&SA[2][e] = mb2;
    }

    unsigned lsense = 0;

    for (int step = 0; step < RELAX + TSTEPS; ++step) {
        const bool  probe = (step >= RELAX);
        const float sv    = probe ? s_sig[step - RELAX] : 0.f;
        const u64   al2   = probe ? f2pk(a_rn, a_rn)   : f2pk(a_rx, a_rx);
        const u64   nI2   = probe ? f2pk(-i_rn, -i_rn) : f2pk(-i_rx, -i_rx);
        const float* __restrict__ m_in  = g_m[(step + 1) & 1];
        float*       __restrict__ m_out = g_m[step & 1];

        // ---- halo refresh from L2, issued first after the barrier ----
        if (live && !sint && step > 0) {
            float2 a = __ldcg((const float2*)&m_in[0*NG + g]);
            float2 b = __ldcg((const float2*)&m_in[1*NG + g]);
            float2 c = __ldcg((const float2*)&m_in[2*NG + g]);
            mb0 = f2pk(a.x, a.y); mb1 = f2pk(b.x, b.y); mb2 = f2pk(c.x, c.y);
            *(u64*)&SA[0][e] = mb0; *(u64*)&SA[1][e] = mb1; *(u64*)&SA[2][e] = mb2;
        }

        const u64 sv2 = f2pk(sv, sv);
        const u64 tB0 = f2fma(sv2, rS0, rB0);
        const u64 tB1 = f2fma(sv2, rS1, rB1);
        const u64 tB2 = f2fma(sv2, rS2, rB2);
        u64 st0 = mb0, st1 = mb1, st2 = mb2;
        u64 ac0 = 0, ac1 = 0, ac2 = 0;   // +0.0 packed
        __syncthreads();

        // one RK substage, fully packed f32x2
        auto stage = [&](const float (*__restrict__ S)[EXT],
                         float (*__restrict__ D)[EXT],
                         u64 coef2, u64 w2, bool last) {
            u64 xm0 = *(const u64*)&S[0][emb];
            u64 xm1 = *(const u64*)&S[1][emb];
            u64 xm2 = *(const u64*)&S[2][emb];
            u64 xp0 = *(const u64*)&S[0][epb];
            u64 xp1 = *(const u64*)&S[1][epb];
            u64 xp2 = *(const u64*)&S[2][epb];
            float lf0 = S[0][yL], lf1 = S[1][yL], lf2 = S[2][yL];
            float rg0 = S[0][yR], rg1 = S[1][yR], rg2 = S[2][yR];
            float s0l, s0h, s1l, s1h, s2l, s2h;
            f2up(st0, s0l, s0h); f2up(st1, s1l, s1h); f2up(st2, s2l, s2h);
            u64 yl0 = f2pk(lf0, s0l), yr0 = f2pk(s0h, rg0);
            u64 yl1 = f2pk(lf1, s1l), yr1 = f2pk(s1h, rg1);
            u64 yl2 = f2pk(lf2, s2l), yr2 = f2pk(s2h, rg2);
            u64 l0 = f2fma(neg4, st0, f2add(f2add(xm0, xp0), f2add(yl0, yr0)));
            u64 l1 = f2fma(neg4, st1, f2add(f2add(xm1, xp1), f2add(yl1, yr1)));
            u64 l2 = f2fma(neg4, st2, f2add(f2add(xm2, xp2), f2add(yl2, yr2)));
            u64 Bx = f2fma(rCL2, l0, tB0);
            u64 By = f2fma(rCL2, l1, tB1);
            u64 Bz = f2fma(nDg2, st2, f2fma(rCL2, l2, tB2));
            u64 n0 = f2neg(st0), n1 = f2neg(st1), n2 = f2neg(st2);
            u64 px = f2fma(st1, Bz, f2mul(n2, By));
            u64 py = f2fma(st2, Bx, f2mul(n0, Bz));
            u64 pz = f2fma(st0, By, f2mul(n1, Bx));
            u64 qx = f2fma(st1, pz, f2mul(n2, py));
            u64 qy = f2fma(st2, px, f2mul(n0, pz));
            u64 qz = f2fma(st0, py, f2mul(n1, px));
            u64 k0 = f2mul(f2fma(al2, qx, px), nI2);
            u64 k1 = f2mul(f2fma(al2, qy, py), nI2);
            u64 k2 = f2mul(f2fma(al2, qz, pz), nI2);
            ac0 = f2fma(w2, k0, ac0);
            ac1 = f2fma(w2, k1, ac1);
            ac2 = f2fma(w2, k2, ac2);
            if (!last) {
                st0 = f2fma(coef2, k0, mb0);
                st1 = f2fma(coef2, k1, mb1);
                st2 = f2fma(coef2, k2, mb2);
                if (live) {
                    *(u64*)&D[0][e] = st0;
                    *(u64*)&D[1][e] = st1;
                    *(u64*)&D[2][e] = st2;
                }
            }
        };

        stage(SA, SB, c052, one2, false); __syncthreads();
        stage(SB, SA, c052, two2, false); __syncthreads();
        stage(SA, SB, cfl2, two2, false); __syncthreads();
        stage(SB, SA, 0,    one2, true);   // k4 folded into acc; no publish

        // ---- final m (interior): SA publish + exchange ring to L2 ----
        float part = 0.f;
        if (sint) {
            mb0 = f2fma(h62, ac0, mb0);
            mb1 = f2fma(h62, ac1, mb1);
            mb2 = f2fma(h62, ac2, mb2);
            float v0l, v0h, v1l, v1h, v2l, v2h;
            f2up(mb0, v0l, v0h); f2up(mb1, v1l, v1h); f2up(mb2, v2l, v2h);
            if (step == RELAX - 1) { m0x[0] = v0l; m0x[1] = v0h; }
            if (probe) part = (v0l - m0x[0]) * pmw[0] + (v0h - m0x[1]) * pmw[1];
            // stage-4 read SB; SA writes race only with next-step reads,
            // separated by gridbar's trailing __syncthreads
            *(u64*)&SA[0][e] = mb0; *(u64*)&SA[1][e] = mb1; *(u64*)&SA[2][e] = mb2;
            if (ring) {
                __stcg((float2*)&m_out[0*NG + g], make_float2(v0l, v0h));
                __stcg((float2*)&m_out[1*NG + g], make_float2(v1l, v1h));
                __stcg((float2*)&m_out[2*NG + g], make_float2(v2l, v2h));
            }
        }

        if (probe && hasp) {
            #pragma unroll
            for (int o = 16; o; o >>= 1) part += __shfl_down_sync(0xffffffffu, part, o);
            if ((tid & 31) == 0) red[tid >> 5] = part;
            __syncthreads();
            if (tid < 32) {
                float v2 = (tid < NT/32) ? red[tid] : 0.f;
                #pragma unroll
                for (int o = 8; o; o >>= 1) v2 += __shfl_down_sync(0xffffffffu, v2, o);
                if (tid == 0) atomicAdd(&out[step - RELAX], v2 * s_pminv);
            }
        }

        gridbar(lsense);
    }
}

// ---------------- host launcher: ONE graph node ----------------
extern "C" void kernel_launch(void* const* d_in, const int* in_sizes, int n_in,
                              void* d_out, int out_size)
{
    const float* sig   = (const float*)d_in[0];
    const float* Bext  = (const float*)d_in[1];
    const float* Msat  = (const float*)d_in[2];
    const float* src   = (const float*)d_in[3];
    const float* pmask = (const float*)d_in[4];
    float* out = (float*)d_out;

    dim3 grid(NBX, NBY);
    k_sim<<<grid, NT>>>(sig, Bext, Msat, src, pmask, out);
}